// round 13
// baseline (speedup 1.0000x reference)
#include <cuda_runtime.h>
#include <cuda_bf16.h>
#include <cstdint>

#define NP   200000
#define NU   50000
#define NNZE 2000000
#define DIM  64
#define NTOT (NP*DIM)      /* 12,800,000 */
#define MSGN (NU*DIM)      /*  3,200,000 */

#define NB_U ((NU + 1023) / 1024)       /* 49  */
#define NB_P ((NP + 1023) / 1024)       /* 196 */
#define SC_BLOCKS ((NNZE + 255) / 256)  /* 7813 */
#define CVT_BLOCKS (NTOT / 4 / 256)     /* 12500 exact */
#define UP_BLOCKS (NU * 32 / 256)       /* 6250 exact */
#define PU_BLOCKS (NP * 32 / 256)       /* 25000 exact */
#define MASK_BLOCKS (NTOT / 2048)       /* 6250 exact: 8 warps x 256 elems */
#define MASK_WORDS (NTOT / 32)          /* 400000 */

__device__ __align__(16) float g_xa[NTOT];                 // layer-1 x
__device__ __align__(16) float g_xb[NTOT];                 // layer-2 x
__device__ __align__(16) __nv_bfloat162 g_xh[NTOT / 2];    // bf16 mirror of current x
__device__ __align__(16) __nv_bfloat162 g_msgh[MSGN / 2];  // bf16 msg (gather operand)
__device__ uint32_t g_mask[MASK_WORDS];                    // packed drop bits (current layer)

// CSR scratch
__device__ int  g_up_ptr[NU + 1];
__device__ int  g_up_off[NU];
__device__ int2 g_up_cv[NNZE];     // packed (col, val-bits), row-grouped
__device__ int  g_pu_ptr[NP + 1];
__device__ int  g_pu_off[NP];
__device__ int2 g_pu_cv[NNZE];
__device__ int  g_bsum_u[64];
__device__ int  g_bsum_p[256];

// ---------------- threefry2x32 (exact JAX semantics) ----------------
__host__ __device__ __forceinline__ uint32_t rotl32(uint32_t x, int d) {
    return (x << d) | (x >> (32 - d));
}

__host__ __device__ __forceinline__ void tf2x32(uint32_t k0, uint32_t k1,
                                                uint32_t x0, uint32_t x1,
                                                uint32_t &o0, uint32_t &o1) {
    uint32_t ks2 = k0 ^ k1 ^ 0x1BD11BDAu;
    x0 += k0; x1 += k1;
#define TFR(r) { x0 += x1; x1 = rotl32(x1, (r)); x1 ^= x0; }
    TFR(13) TFR(15) TFR(26) TFR(6)
    x0 += k1;  x1 += ks2 + 1u;
    TFR(17) TFR(29) TFR(16) TFR(24)
    x0 += ks2; x1 += k0 + 2u;
    TFR(13) TFR(15) TFR(26) TFR(6)
    x0 += k0;  x1 += k1 + 3u;
    TFR(17) TFR(29) TFR(16) TFR(24)
    x0 += k1;  x1 += ks2 + 4u;
    TFR(13) TFR(15) TFR(26) TFR(6)
    x0 += ks2; x1 += k0 + 5u;
#undef TFR
    o0 = x0; o1 = x1;
}

// partitionable threefry draw for element e (counter (0, e)), 32-bit: out0 ^ out1
__device__ __forceinline__ uint32_t tf_bits(uint32_t k0, uint32_t k1, uint32_t e) {
    uint32_t o0, o1;
    tf2x32(k0, k1, 0u, e, o0, o1);
    return o0 ^ o1;
}

// ---------------- CSR build ----------------
__global__ void zero_cnt_kernel() {
    int i = blockIdx.x * blockDim.x + threadIdx.x;
    if (i <= NU) g_up_ptr[i] = 0;
    if (i <= NP) g_pu_ptr[i] = 0;
}

__global__ void hist_kernel(const int* __restrict__ up_rows,
                            const int* __restrict__ pu_rows) {
    int e = blockIdx.x * blockDim.x + threadIdx.x;
    if (e >= NNZE) return;
    atomicAdd(&g_up_ptr[__ldg(up_rows + e)], 1);
    atomicAdd(&g_pu_ptr[__ldg(pu_rows + e)], 1);
}

// merged pass 1: blocks [0,NB_U) scan UP counts, [NB_U,NB_U+NB_P) scan PU counts
__global__ void scan1_kernel() {
    __shared__ int ws[32];
    int t = threadIdx.x;
    bool isU = blockIdx.x < NB_U;
    int lb = isU ? blockIdx.x : blockIdx.x - NB_U;
    int n  = isU ? NU : NP;
    const int* cnt = isU ? g_up_ptr : g_pu_ptr;
    int* excl      = isU ? g_up_off : g_pu_off;
    int* bsum      = isU ? g_bsum_u : g_bsum_p;

    int i = lb * 1024 + t;
    int v = (i < n) ? cnt[i] : 0;
    int x = v;
#pragma unroll
    for (int d = 1; d < 32; d <<= 1) {
        int u = __shfl_up_sync(~0u, x, d);
        if ((t & 31) >= d) x += u;
    }
    if ((t & 31) == 31) ws[t >> 5] = x;
    __syncthreads();
    if (t < 32) {
        int w = ws[t];
#pragma unroll
        for (int d = 1; d < 32; d <<= 1) {
            int u = __shfl_up_sync(~0u, w, d);
            if (t >= d) w += u;
        }
        ws[t] = w;
    }
    __syncthreads();
    int base = (t >= 32) ? ws[(t >> 5) - 1] : 0;
    int incl = x + base;
    if (i < n) excl[i] = incl - v;
    if (t == 1023) bsum[lb] = incl;
}

// merged pass 2: block 0 scans UP block sums, block 1 scans PU block sums
__global__ void scan2_kernel() {
    __shared__ int ws[8];
    bool isU = blockIdx.x == 0;
    int nb   = isU ? NB_U : NB_P;
    int* bsum  = isU ? g_bsum_u : g_bsum_p;
    int* ptr_n = isU ? &g_up_ptr[NU] : &g_pu_ptr[NP];

    int t = threadIdx.x;       // 256 threads
    int v = (t < nb) ? bsum[t] : 0;
    int x = v;
#pragma unroll
    for (int d = 1; d < 32; d <<= 1) {
        int u = __shfl_up_sync(~0u, x, d);
        if ((t & 31) >= d) x += u;
    }
    if ((t & 31) == 31) ws[t >> 5] = x;
    __syncthreads();
    if (t < 8) {
        int w = ws[t];
#pragma unroll
        for (int d = 1; d < 8; d <<= 1) {
            int u = __shfl_up_sync(0xffu, w, d);
            if (t >= d) w += u;
        }
        ws[t] = w;
    }
    __syncthreads();
    int base = (t >= 32) ? ws[(t >> 5) - 1] : 0;
    int incl = x + base;
    if (t < nb) bsum[t] = incl - v;
    if (t == nb - 1) *ptr_n = incl;
}

// merged pass 3: add block offset; write both ptr and off
__global__ void scan3_kernel() {
    bool isU = blockIdx.x < NB_U;
    int lb = isU ? blockIdx.x : blockIdx.x - NB_U;
    int n  = isU ? NU : NP;
    int* ptr = isU ? g_up_ptr : g_pu_ptr;
    int* off = isU ? g_up_off : g_pu_off;
    const int* bsum = isU ? g_bsum_u : g_bsum_p;

    int i = lb * 1024 + threadIdx.x;
    if (i < n) {
        int v = off[i] + bsum[lb];
        ptr[i] = v;
        off[i] = v;
    }
}

// ---------------- launch A: scatter UP entries || cvt pois -> bf16 ----------
__global__ void scatter_up_cvt_kernel(const int* __restrict__ up_rows,
                                      const int* __restrict__ up_cols,
                                      const float* __restrict__ up_vals,
                                      const float4* __restrict__ pois) {
    if (blockIdx.x < SC_BLOCKS) {
        int e = blockIdx.x * 256 + threadIdx.x;
        if (e >= NNZE) return;
        int r = __ldg(up_rows + e);
        int p = atomicAdd(&g_up_off[r], 1);
        g_up_cv[p] = make_int2(__ldg(up_cols + e), __float_as_int(__ldg(up_vals + e)));
    } else {
        int i = (blockIdx.x - SC_BLOCKS) * 256 + threadIdx.x;  // < NTOT/4 exact
        float4 v = pois[i];
        g_xh[2 * i]     = __floats2bfloat162_rn(v.x, v.y);
        g_xh[2 * i + 1] = __floats2bfloat162_rn(v.z, v.w);
    }
}

// ---------------- work bodies ----------------
// UP SpMM body (warp per U-row; bf16 gather, fp32 accum) — round-11 loop
__device__ __forceinline__ void spmm_up_body(int b, int tid) {
    int w = (b * 256 + tid) >> 5;                    // < NU exact
    int lane = tid & 31;
    int s = __ldg(g_up_ptr + w), e = __ldg(g_up_ptr + w + 1);
    float accx = 0.f, accy = 0.f;
    for (int j = s; j < e; ++j) {
        int2 cv = __ldg(g_up_cv + j);                // same addr all lanes: broadcast
        float v = __int_as_float(cv.y);
        float2 xv = __bfloat1622float2(g_xh[(size_t)cv.x * (DIM / 2) + lane]);
        accx += v * xv.x;
        accy += v * xv.y;
    }
    g_msgh[(size_t)w * (DIM / 2) + lane] = __floats2bfloat162_rn(accx, accy);
}

// maskgen body: block b's 8 warps each cover 256 elements -> 8 ballot words
__device__ __forceinline__ void maskgen_body(int b, int tid,
                                             uint32_t k0, uint32_t k1) {
    int lane = tid & 31;
    int wm = b * 8 + (tid >> 5);                     // global mask-warp id
    uint32_t ebase = (uint32_t)wm * 256u + (uint32_t)lane;
#pragma unroll
    for (int i = 0; i < 8; ++i) {
        uint32_t bits = tf_bits(k0, k1, ebase + (uint32_t)(i * 32));
        uint32_t bal = __ballot_sync(~0u, bits >> 31);   // 1 = drop
        if (lane == 0) g_mask[wm * 8 + i] = bal;
    }
}

// ---------------- launch B: UP0 || maskgen0 || scatter PU (3-way interleave)
__global__ void up0_mask_scatter_kernel(const int* __restrict__ pu_rows,
                                        const int* __restrict__ pu_cols,
                                        const float* __restrict__ pu_vals,
                                        uint32_t k0, uint32_t k1) {
    int bid = blockIdx.x;
    int e;
    if (bid < 3 * UP_BLOCKS) {
        int r = bid % 3, b = bid / 3;
        if (r == 0) { spmm_up_body(b, threadIdx.x); return; }
        if (r == 1) { maskgen_body(b, threadIdx.x, k0, k1); return; }
        e = b * 256 + threadIdx.x;                   // b < 6250 -> e < NNZE
    } else {
        e = (bid - 3 * UP_BLOCKS + UP_BLOCKS) * 256 + threadIdx.x;
        if (e >= NNZE) return;
    }
    int r = __ldg(pu_rows + e);
    int p = atomicAdd(&g_pu_off[r], 1);
    g_pu_cv[p] = make_int2(__ldg(pu_cols + e), __float_as_int(__ldg(pu_vals + e)));
}

// ---------------- layers 1,2: UP SpMM || maskgen, parity-interleaved --------
__global__ void up_mask_kernel(uint32_t k0, uint32_t k1) {
    int b = blockIdx.x >> 1;
    if (blockIdx.x & 1) maskgen_body(b, threadIdx.x, k0, k1);
    else                spmm_up_body(b, threadIdx.x);
}

// ---------------- PU SpMM fused with residual + dropout (+ final mean) ------
// last==0: x_next = drop(prop + x_in); write x_next (fp32 -> x_out, bf16 -> g_xh)
// last==1: out = 0.25*(pois + x1 + x_in + drop(prop + x_in))
__global__ void spmm_pu_fused_kernel(const float* __restrict__ x_in,
                                     float* __restrict__ x_out,
                                     const float* __restrict__ pois_in,
                                     const float* __restrict__ x1_in,
                                     int last, float* __restrict__ out) {
    int w = (blockIdx.x * 256 + threadIdx.x) >> 5;       // < NP exact
    int lane = threadIdx.x & 31;
    int s = __ldg(g_pu_ptr + w), e = __ldg(g_pu_ptr + w + 1);
    float accx = 0.f, accy = 0.f;
    for (int j = s; j < e; ++j) {
        int2 cv = __ldg(g_pu_cv + j);                    // broadcast load
        float v = __int_as_float(cv.y);
        float2 xv = __bfloat1622float2(g_msgh[(size_t)cv.x * (DIM / 2) + lane]);
        accx += v * xv.x;
        accy += v * xv.y;
    }
    size_t idx = (size_t)w * DIM + lane * 2;

    uint32_t word = __ldg(&g_mask[2 * w + (lane >> 4)]); // broadcast: 2 words/warp
    int sh = (lane & 15) * 2;

    float2 xv = *reinterpret_cast<const float2*>(x_in + idx);
    float n0 = ((word >> sh)       & 1u) ? 0.f : 2.f * (accx + xv.x);
    float n1 = ((word >> (sh + 1)) & 1u) ? 0.f : 2.f * (accy + xv.y);

    if (last) {
        float2 pv = *reinterpret_cast<const float2*>(pois_in + idx);
        float2 x1 = *reinterpret_cast<const float2*>(x1_in + idx);
        *reinterpret_cast<float2*>(out + idx) =
            make_float2((pv.x + x1.x + xv.x + n0) * 0.25f,
                        (pv.y + x1.y + xv.y + n1) * 0.25f);
    } else {
        *reinterpret_cast<float2*>(x_out + idx) = make_float2(n0, n1);
        g_xh[idx / 2] = __floats2bfloat162_rn(n0, n1);
    }
}

// ---------------- launch ----------------
// Inputs in dict/insertion order:
//   d_in[0]=pois_embs, d_in[1]=up_rows, d_in[2]=up_cols, d_in[3]=up_vals,
//   d_in[4]=pu_rows,   d_in[5]=pu_cols, d_in[6]=pu_vals
extern "C" void kernel_launch(void* const* d_in, const int* in_sizes, int n_in,
                              void* d_out, int out_size) {
    const float* pois    = (const float*)d_in[0];
    const int*   up_rows = (const int*)  d_in[1];
    const int*   up_cols = (const int*)  d_in[2];
    const float* up_vals = (const float*)d_in[3];
    const int*   pu_rows = (const int*)  d_in[4];
    const int*   pu_cols = (const int*)  d_in[5];
    const float* pu_vals = (const float*)d_in[6];
    float* out = (float*)d_out;

    float *pxa, *pxb;
    cudaGetSymbolAddress((void**)&pxa, g_xa);
    cudaGetSymbolAddress((void**)&pxb, g_xb);

    // per-layer dropout keys: fold_in(key(42), l) = threefry((0,42),(0,l))
    uint32_t lk0[3], lk1[3];
    for (int l = 0; l < 3; ++l)
        tf2x32(0u, 42u, 0u, (uint32_t)l, lk0[l], lk1[l]);

    const int B = 256;

    // ---- CSR build (once per call, reused by all 3 layers) ----
    zero_cnt_kernel<<<(NP + 1 + B - 1) / B, B>>>();
    hist_kernel<<<SC_BLOCKS, B>>>(up_rows, pu_rows);
    scan1_kernel<<<NB_U + NB_P, 1024>>>();
    scan2_kernel<<<2, 256>>>();
    scan3_kernel<<<NB_U + NB_P, 1024>>>();

    // launch A: scatter UP || cvt pois->bf16
    scatter_up_cvt_kernel<<<SC_BLOCKS + CVT_BLOCKS, B>>>(up_rows, up_cols, up_vals,
                                                         (const float4*)pois);
    // launch B: UP SpMM layer 0 || maskgen layer 0 || scatter PU (interleaved)
    up0_mask_scatter_kernel<<<3 * UP_BLOCKS + (SC_BLOCKS - UP_BLOCKS), B>>>(
        pu_rows, pu_cols, pu_vals, lk0[0], lk1[0]);

    // ---- layers (lazy acc: mean folded at last layer) ----
    // layer 0 PU: x_in = pois -> x1 in g_xa
    spmm_pu_fused_kernel<<<PU_BLOCKS, B>>>(pois, pxa, nullptr, nullptr, 0, out);
    // layer 1
    up_mask_kernel<<<2 * UP_BLOCKS, B>>>(lk0[1], lk1[1]);
    spmm_pu_fused_kernel<<<PU_BLOCKS, B>>>(pxa, pxb, nullptr, nullptr, 0, out);
    // layer 2: out = 0.25*(pois + x1 + x2 + x3)
    up_mask_kernel<<<2 * UP_BLOCKS, B>>>(lk0[2], lk1[2]);
    spmm_pu_fused_kernel<<<PU_BLOCKS, B>>>(pxb, nullptr, pois, pxa, 1, out);
}

// round 14
// speedup vs baseline: 1.2557x; 1.2557x over previous
#include <cuda_runtime.h>
#include <cuda_bf16.h>
#include <cstdint>

#define NP   200000
#define NU   50000
#define NNZE 2000000
#define DIM  64
#define NTOT (NP*DIM)      /* 12,800,000 */
#define MSGN (NU*DIM)      /*  3,200,000 */

#define NB_U ((NU + 1023) / 1024)       /* 49  */
#define NB_P ((NP + 1023) / 1024)       /* 196 */
#define SC_BLOCKS ((NNZE + 255) / 256)  /* 7813 */
#define CVT_BLOCKS (NTOT / 4 / 256)     /* 12500 exact */
#define UP_BLOCKS (NU * 32 / 256)       /* 6250 exact */
#define PU_BLOCKS (NP * 16 / 256)       /* 12500 exact: half-warp per row */

__device__ __align__(16) float g_xa[NTOT];                 // layer-1 x
__device__ __align__(16) float g_xb[NTOT];                 // layer-2 x
__device__ __align__(16) __nv_bfloat162 g_xh[NTOT / 2];    // bf16 mirror of current x
__device__ __align__(16) __nv_bfloat162 g_msgh[MSGN / 2];  // bf16 msg (gather operand)

// CSR scratch
__device__ int  g_up_ptr[NU + 1];
__device__ int  g_up_off[NU];
__device__ int2 g_up_cv[NNZE];     // packed (col, val-bits), row-grouped
__device__ int  g_pu_ptr[NP + 1];
__device__ int  g_pu_off[NP];
__device__ int2 g_pu_cv[NNZE];
__device__ int  g_bsum_u[64];
__device__ int  g_bsum_p[256];

// ---------------- threefry2x32 (exact JAX semantics) ----------------
__host__ __device__ __forceinline__ uint32_t rotl32(uint32_t x, int d) {
    return (x << d) | (x >> (32 - d));
}

__host__ __device__ __forceinline__ void tf2x32(uint32_t k0, uint32_t k1,
                                                uint32_t x0, uint32_t x1,
                                                uint32_t &o0, uint32_t &o1) {
    uint32_t ks2 = k0 ^ k1 ^ 0x1BD11BDAu;
    x0 += k0; x1 += k1;
#define TFR(r) { x0 += x1; x1 = rotl32(x1, (r)); x1 ^= x0; }
    TFR(13) TFR(15) TFR(26) TFR(6)
    x0 += k1;  x1 += ks2 + 1u;
    TFR(17) TFR(29) TFR(16) TFR(24)
    x0 += ks2; x1 += k0 + 2u;
    TFR(13) TFR(15) TFR(26) TFR(6)
    x0 += k0;  x1 += k1 + 3u;
    TFR(17) TFR(29) TFR(16) TFR(24)
    x0 += k1;  x1 += ks2 + 4u;
    TFR(13) TFR(15) TFR(26) TFR(6)
    x0 += ks2; x1 += k0 + 5u;
#undef TFR
    o0 = x0; o1 = x1;
}

// partitionable threefry draw for element e (counter (0, e)), 32-bit: out0 ^ out1
__device__ __forceinline__ uint32_t tf_bits(uint32_t k0, uint32_t k1, uint32_t e) {
    uint32_t o0, o1;
    tf2x32(k0, k1, 0u, e, o0, o1);
    return o0 ^ o1;
}

__device__ __forceinline__ float dropv(uint32_t bits, float s) {
    return (bits & 0x80000000u) ? 0.f : 2.f * s;   // keep iff MSB==0, scale 1/keep=2
}

__device__ __forceinline__ float2 bf2f(uint32_t raw) {
    return __bfloat1622float2(*reinterpret_cast<__nv_bfloat162*>(&raw));
}

// ---------------- CSR build ----------------
__global__ void zero_cnt_kernel() {
    int i = blockIdx.x * blockDim.x + threadIdx.x;
    if (i <= NU) g_up_ptr[i] = 0;
    if (i <= NP) g_pu_ptr[i] = 0;
}

__global__ void hist_kernel(const int* __restrict__ up_rows,
                            const int* __restrict__ pu_rows) {
    int e = blockIdx.x * blockDim.x + threadIdx.x;
    if (e >= NNZE) return;
    atomicAdd(&g_up_ptr[__ldg(up_rows + e)], 1);
    atomicAdd(&g_pu_ptr[__ldg(pu_rows + e)], 1);
}

// merged pass 1: blocks [0,NB_U) scan UP counts, [NB_U,NB_U+NB_P) scan PU counts
__global__ void scan1_kernel() {
    __shared__ int ws[32];
    int t = threadIdx.x;
    bool isU = blockIdx.x < NB_U;
    int lb = isU ? blockIdx.x : blockIdx.x - NB_U;
    int n  = isU ? NU : NP;
    const int* cnt = isU ? g_up_ptr : g_pu_ptr;
    int* excl      = isU ? g_up_off : g_pu_off;
    int* bsum      = isU ? g_bsum_u : g_bsum_p;

    int i = lb * 1024 + t;
    int v = (i < n) ? cnt[i] : 0;
    int x = v;
#pragma unroll
    for (int d = 1; d < 32; d <<= 1) {
        int u = __shfl_up_sync(~0u, x, d);
        if ((t & 31) >= d) x += u;
    }
    if ((t & 31) == 31) ws[t >> 5] = x;
    __syncthreads();
    if (t < 32) {
        int w = ws[t];
#pragma unroll
        for (int d = 1; d < 32; d <<= 1) {
            int u = __shfl_up_sync(~0u, w, d);
            if (t >= d) w += u;
        }
        ws[t] = w;
    }
    __syncthreads();
    int base = (t >= 32) ? ws[(t >> 5) - 1] : 0;
    int incl = x + base;
    if (i < n) excl[i] = incl - v;
    if (t == 1023) bsum[lb] = incl;
}

// merged pass 2: block 0 scans UP block sums, block 1 scans PU block sums
__global__ void scan2_kernel() {
    __shared__ int ws[8];
    bool isU = blockIdx.x == 0;
    int nb   = isU ? NB_U : NB_P;
    int* bsum  = isU ? g_bsum_u : g_bsum_p;
    int* ptr_n = isU ? &g_up_ptr[NU] : &g_pu_ptr[NP];

    int t = threadIdx.x;       // 256 threads
    int v = (t < nb) ? bsum[t] : 0;
    int x = v;
#pragma unroll
    for (int d = 1; d < 32; d <<= 1) {
        int u = __shfl_up_sync(~0u, x, d);
        if ((t & 31) >= d) x += u;
    }
    if ((t & 31) == 31) ws[t >> 5] = x;
    __syncthreads();
    if (t < 8) {
        int w = ws[t];
#pragma unroll
        for (int d = 1; d < 8; d <<= 1) {
            int u = __shfl_up_sync(0xffu, w, d);
            if (t >= d) w += u;
        }
        ws[t] = w;
    }
    __syncthreads();
    int base = (t >= 32) ? ws[(t >> 5) - 1] : 0;
    int incl = x + base;
    if (t < nb) bsum[t] = incl - v;
    if (t == nb - 1) *ptr_n = incl;
}

// merged pass 3: add block offset; write both ptr and off
__global__ void scan3_kernel() {
    bool isU = blockIdx.x < NB_U;
    int lb = isU ? blockIdx.x : blockIdx.x - NB_U;
    int n  = isU ? NU : NP;
    int* ptr = isU ? g_up_ptr : g_pu_ptr;
    int* off = isU ? g_up_off : g_pu_off;
    const int* bsum = isU ? g_bsum_u : g_bsum_p;

    int i = lb * 1024 + threadIdx.x;
    if (i < n) {
        int v = off[i] + bsum[lb];
        ptr[i] = v;
        off[i] = v;
    }
}

// ---------------- launch A: scatter UP entries || cvt pois -> bf16 ----------
__global__ void scatter_up_cvt_kernel(const int* __restrict__ up_rows,
                                      const int* __restrict__ up_cols,
                                      const float* __restrict__ up_vals,
                                      const float4* __restrict__ pois) {
    if (blockIdx.x < SC_BLOCKS) {
        int e = blockIdx.x * 256 + threadIdx.x;
        if (e >= NNZE) return;
        int r = __ldg(up_rows + e);
        int p = atomicAdd(&g_up_off[r], 1);
        g_up_cv[p] = make_int2(__ldg(up_cols + e), __float_as_int(__ldg(up_vals + e)));
    } else {
        int i = (blockIdx.x - SC_BLOCKS) * 256 + threadIdx.x;  // < NTOT/4 exact
        float4 v = pois[i];
        g_xh[2 * i]     = __floats2bfloat162_rn(v.x, v.y);
        g_xh[2 * i + 1] = __floats2bfloat162_rn(v.z, v.w);
    }
}

// ---------------- UP SpMM body (warp per U-row; bf16 gather, fp32 accum) ----
__device__ __forceinline__ void spmm_up_body(int w, int lane) {
    int s = __ldg(g_up_ptr + w), e = __ldg(g_up_ptr + w + 1);
    float accx = 0.f, accy = 0.f;
    for (int j = s; j < e; ++j) {
        int2 cv = __ldg(g_up_cv + j);                // same addr all lanes: broadcast
        float v = __int_as_float(cv.y);
        float2 xv = __bfloat1622float2(g_xh[(size_t)cv.x * (DIM / 2) + lane]);
        accx += v * xv.x;
        accy += v * xv.y;
    }
    g_msgh[(size_t)w * (DIM / 2) + lane] = __floats2bfloat162_rn(accx, accy);
}

// ---------------- launch B: UP SpMM layer 0 || scatter PU entries ----------
__global__ void up0_scatter_pu_kernel(const int* __restrict__ pu_rows,
                                      const int* __restrict__ pu_cols,
                                      const float* __restrict__ pu_vals) {
    if (blockIdx.x < UP_BLOCKS) {
        int w = (blockIdx.x * 256 + threadIdx.x) >> 5;   // < NU exact
        spmm_up_body(w, threadIdx.x & 31);
    } else {
        int e = (blockIdx.x - UP_BLOCKS) * 256 + threadIdx.x;
        if (e >= NNZE) return;
        int r = __ldg(pu_rows + e);
        int p = atomicAdd(&g_pu_off[r], 1);
        g_pu_cv[p] = make_int2(__ldg(pu_cols + e), __float_as_int(__ldg(pu_vals + e)));
    }
}

// plain UP SpMM for layers 1, 2
__global__ void spmm_up_kernel() {
    int w = (blockIdx.x * 256 + threadIdx.x) >> 5;       // < NU exact
    spmm_up_body(w, threadIdx.x & 31);
}

// ---------------- PU SpMM fused: half-warp per row (two independent rows) ---
// lane = 16*h + sl; half-warp h owns row w = 2*g + h (g = global half-pair id).
// lane gathers uint2 (4 bf16) at positions [sl*4, sl*4+4) of the msg row.
// Epilogue: float4 on elements [w*64 + sl*4, +4); threefry inline (exact).
__global__ void spmm_pu_fused_kernel(const float* __restrict__ x_in,
                                     float* __restrict__ x_out,
                                     const float* __restrict__ pois_in,
                                     const float* __restrict__ x1_in,
                                     uint32_t k0, uint32_t k1, int last,
                                     float* __restrict__ out) {
    int g = (blockIdx.x * 256 + threadIdx.x) >> 5;       // < NP/2 exact
    int lane = threadIdx.x & 31;
    int h = lane >> 4, sl = lane & 15;
    int w = 2 * g + h;                                   // this half-warp's row
    int s = __ldg(g_pu_ptr + w), e = __ldg(g_pu_ptr + w + 1);
    float a0 = 0.f, a1 = 0.f, a2 = 0.f, a3 = 0.f;
    const uint2* mbase = reinterpret_cast<const uint2*>(g_msgh);
    for (int j = s; j < e; ++j) {
        int2 cv = __ldg(g_pu_cv + j);                // same addr in half-warp: broadcast
        float v = __int_as_float(cv.y);
        uint2 raw = __ldg(mbase + (size_t)cv.x * 16 + sl);
        float2 p0 = bf2f(raw.x), p1 = bf2f(raw.y);
        a0 += v * p0.x; a1 += v * p0.y;
        a2 += v * p1.x; a3 += v * p1.y;
    }

    size_t idx = (size_t)w * DIM + sl * 4;
    uint32_t e0 = (uint32_t)idx;
    uint32_t b0 = tf_bits(k0, k1, e0);
    uint32_t b1 = tf_bits(k0, k1, e0 + 1u);
    uint32_t b2 = tf_bits(k0, k1, e0 + 2u);
    uint32_t b3 = tf_bits(k0, k1, e0 + 3u);

    float4 xv = *reinterpret_cast<const float4*>(x_in + idx);
    float n0 = dropv(b0, a0 + xv.x);
    float n1 = dropv(b1, a1 + xv.y);
    float n2 = dropv(b2, a2 + xv.z);
    float n3 = dropv(b3, a3 + xv.w);

    if (last) {
        float4 pv = *reinterpret_cast<const float4*>(pois_in + idx);
        float4 x1 = *reinterpret_cast<const float4*>(x1_in + idx);
        *reinterpret_cast<float4*>(out + idx) =
            make_float4((pv.x + x1.x + xv.x + n0) * 0.25f,
                        (pv.y + x1.y + xv.y + n1) * 0.25f,
                        (pv.z + x1.z + xv.z + n2) * 0.25f,
                        (pv.w + x1.w + xv.w + n3) * 0.25f);
    } else {
        *reinterpret_cast<float4*>(x_out + idx) = make_float4(n0, n1, n2, n3);
        g_xh[idx / 2]     = __floats2bfloat162_rn(n0, n1);
        g_xh[idx / 2 + 1] = __floats2bfloat162_rn(n2, n3);
    }
}

// ---------------- launch ----------------
// Inputs in dict/insertion order:
//   d_in[0]=pois_embs, d_in[1]=up_rows, d_in[2]=up_cols, d_in[3]=up_vals,
//   d_in[4]=pu_rows,   d_in[5]=pu_cols, d_in[6]=pu_vals
extern "C" void kernel_launch(void* const* d_in, const int* in_sizes, int n_in,
                              void* d_out, int out_size) {
    const float* pois    = (const float*)d_in[0];
    const int*   up_rows = (const int*)  d_in[1];
    const int*   up_cols = (const int*)  d_in[2];
    const float* up_vals = (const float*)d_in[3];
    const int*   pu_rows = (const int*)  d_in[4];
    const int*   pu_cols = (const int*)  d_in[5];
    const float* pu_vals = (const float*)d_in[6];
    float* out = (float*)d_out;

    float *pxa, *pxb;
    cudaGetSymbolAddress((void**)&pxa, g_xa);
    cudaGetSymbolAddress((void**)&pxb, g_xb);

    // per-layer dropout keys: fold_in(key(42), l) = threefry((0,42),(0,l))
    uint32_t lk0[3], lk1[3];
    for (int l = 0; l < 3; ++l)
        tf2x32(0u, 42u, 0u, (uint32_t)l, lk0[l], lk1[l]);

    const int B = 256;

    // ---- CSR build (once per call, reused by all 3 layers) ----
    zero_cnt_kernel<<<(NP + 1 + B - 1) / B, B>>>();
    hist_kernel<<<SC_BLOCKS, B>>>(up_rows, pu_rows);
    scan1_kernel<<<NB_U + NB_P, 1024>>>();
    scan2_kernel<<<2, 256>>>();
    scan3_kernel<<<NB_U + NB_P, 1024>>>();

    // launch A: scatter UP || cvt pois->bf16
    scatter_up_cvt_kernel<<<SC_BLOCKS + CVT_BLOCKS, B>>>(up_rows, up_cols, up_vals,
                                                         (const float4*)pois);
    // launch B: UP SpMM layer 0 || scatter PU
    up0_scatter_pu_kernel<<<UP_BLOCKS + SC_BLOCKS, B>>>(pu_rows, pu_cols, pu_vals);

    // ---- layers (lazy acc: mean folded at last layer) ----
    // layer 0 PU: x_in = pois -> x1 in g_xa
    spmm_pu_fused_kernel<<<PU_BLOCKS, B>>>(pois, pxa, nullptr, nullptr,
                                           lk0[0], lk1[0], 0, out);
    // layer 1
    spmm_up_kernel<<<UP_BLOCKS, B>>>();
    spmm_pu_fused_kernel<<<PU_BLOCKS, B>>>(pxa, pxb, nullptr, nullptr,
                                           lk0[1], lk1[1], 0, out);
    // layer 2: out = 0.25*(pois + x1 + x2 + x3)
    spmm_up_kernel<<<UP_BLOCKS, B>>>();
    spmm_pu_fused_kernel<<<PU_BLOCKS, B>>>(pxb, nullptr, pois, pxa,
                                           lk0[2], lk1[2], 1, out);
}

// round 15
// speedup vs baseline: 1.3466x; 1.0724x over previous
#include <cuda_runtime.h>
#include <cuda_bf16.h>
#include <cstdint>

#define NP   200000
#define NU   50000
#define NNZE 2000000
#define DIM  64
#define NTOT (NP*DIM)      /* 12,800,000 */
#define MSGN (NU*DIM)      /*  3,200,000 */

#define NB_U ((NU + 1023) / 1024)       /* 49  */
#define NB_P ((NP + 1023) / 1024)       /* 196 */
#define SC_BLOCKS ((NNZE + 255) / 256)  /* 7813 */
#define CVT_BLOCKS (NTOT / 4 / 256)     /* 12500 exact */
#define UP_BLOCKS (NU * 16 / 256)       /* 3125 exact: half-warp per row */
#define PU_BLOCKS (NP * 16 / 256)       /* 12500 exact: half-warp per row */

__device__ __align__(16) float g_xa[NTOT];                 // layer-1 x
__device__ __align__(16) float g_xb[NTOT];                 // layer-2 x
__device__ __align__(16) __nv_bfloat162 g_xh[NTOT / 2];    // bf16 mirror of current x
__device__ __align__(16) __nv_bfloat162 g_msgh[MSGN / 2];  // bf16 msg (gather operand)

// CSR scratch
__device__ int  g_up_ptr[NU + 1];
__device__ int  g_up_off[NU];
__device__ int2 g_up_cv[NNZE];     // packed (col, val-bits), row-grouped
__device__ int  g_pu_ptr[NP + 1];
__device__ int  g_pu_off[NP];
__device__ int2 g_pu_cv[NNZE];
__device__ int  g_bsum_u[64];
__device__ int  g_bsum_p[256];

// ---------------- threefry2x32 (exact JAX semantics) ----------------
__host__ __device__ __forceinline__ uint32_t rotl32(uint32_t x, int d) {
    return (x << d) | (x >> (32 - d));
}

__host__ __device__ __forceinline__ void tf2x32(uint32_t k0, uint32_t k1,
                                                uint32_t x0, uint32_t x1,
                                                uint32_t &o0, uint32_t &o1) {
    uint32_t ks2 = k0 ^ k1 ^ 0x1BD11BDAu;
    x0 += k0; x1 += k1;
#define TFR(r) { x0 += x1; x1 = rotl32(x1, (r)); x1 ^= x0; }
    TFR(13) TFR(15) TFR(26) TFR(6)
    x0 += k1;  x1 += ks2 + 1u;
    TFR(17) TFR(29) TFR(16) TFR(24)
    x0 += ks2; x1 += k0 + 2u;
    TFR(13) TFR(15) TFR(26) TFR(6)
    x0 += k0;  x1 += k1 + 3u;
    TFR(17) TFR(29) TFR(16) TFR(24)
    x0 += k1;  x1 += ks2 + 4u;
    TFR(13) TFR(15) TFR(26) TFR(6)
    x0 += ks2; x1 += k0 + 5u;
#undef TFR
    o0 = x0; o1 = x1;
}

// partitionable threefry draw for element e (counter (0, e)), 32-bit: out0 ^ out1
__device__ __forceinline__ uint32_t tf_bits(uint32_t k0, uint32_t k1, uint32_t e) {
    uint32_t o0, o1;
    tf2x32(k0, k1, 0u, e, o0, o1);
    return o0 ^ o1;
}

__device__ __forceinline__ float dropv(uint32_t bits, float s) {
    return (bits & 0x80000000u) ? 0.f : 2.f * s;   // keep iff MSB==0, scale 1/keep=2
}

__device__ __forceinline__ float2 bf2f(uint32_t raw) {
    return __bfloat1622float2(*reinterpret_cast<__nv_bfloat162*>(&raw));
}

// ---------------- CSR build ----------------
__global__ void zero_cnt_kernel() {
    int i = blockIdx.x * blockDim.x + threadIdx.x;
    if (i <= NU) g_up_ptr[i] = 0;
    if (i <= NP) g_pu_ptr[i] = 0;
}

__global__ void hist_kernel(const int* __restrict__ up_rows,
                            const int* __restrict__ pu_rows) {
    int e = blockIdx.x * blockDim.x + threadIdx.x;
    if (e >= NNZE) return;
    atomicAdd(&g_up_ptr[__ldg(up_rows + e)], 1);
    atomicAdd(&g_pu_ptr[__ldg(pu_rows + e)], 1);
}

// merged pass 1: blocks [0,NB_U) scan UP counts, [NB_U,NB_U+NB_P) scan PU counts
__global__ void scan1_kernel() {
    __shared__ int ws[32];
    int t = threadIdx.x;
    bool isU = blockIdx.x < NB_U;
    int lb = isU ? blockIdx.x : blockIdx.x - NB_U;
    int n  = isU ? NU : NP;
    const int* cnt = isU ? g_up_ptr : g_pu_ptr;
    int* excl      = isU ? g_up_off : g_pu_off;
    int* bsum      = isU ? g_bsum_u : g_bsum_p;

    int i = lb * 1024 + t;
    int v = (i < n) ? cnt[i] : 0;
    int x = v;
#pragma unroll
    for (int d = 1; d < 32; d <<= 1) {
        int u = __shfl_up_sync(~0u, x, d);
        if ((t & 31) >= d) x += u;
    }
    if ((t & 31) == 31) ws[t >> 5] = x;
    __syncthreads();
    if (t < 32) {
        int w = ws[t];
#pragma unroll
        for (int d = 1; d < 32; d <<= 1) {
            int u = __shfl_up_sync(~0u, w, d);
            if (t >= d) w += u;
        }
        ws[t] = w;
    }
    __syncthreads();
    int base = (t >= 32) ? ws[(t >> 5) - 1] : 0;
    int incl = x + base;
    if (i < n) excl[i] = incl - v;
    if (t == 1023) bsum[lb] = incl;
}

// merged pass 2: block 0 scans UP block sums, block 1 scans PU block sums
__global__ void scan2_kernel() {
    __shared__ int ws[8];
    bool isU = blockIdx.x == 0;
    int nb   = isU ? NB_U : NB_P;
    int* bsum  = isU ? g_bsum_u : g_bsum_p;
    int* ptr_n = isU ? &g_up_ptr[NU] : &g_pu_ptr[NP];

    int t = threadIdx.x;       // 256 threads
    int v = (t < nb) ? bsum[t] : 0;
    int x = v;
#pragma unroll
    for (int d = 1; d < 32; d <<= 1) {
        int u = __shfl_up_sync(~0u, x, d);
        if ((t & 31) >= d) x += u;
    }
    if ((t & 31) == 31) ws[t >> 5] = x;
    __syncthreads();
    if (t < 8) {
        int w = ws[t];
#pragma unroll
        for (int d = 1; d < 8; d <<= 1) {
            int u = __shfl_up_sync(0xffu, w, d);
            if (t >= d) w += u;
        }
        ws[t] = w;
    }
    __syncthreads();
    int base = (t >= 32) ? ws[(t >> 5) - 1] : 0;
    int incl = x + base;
    if (t < nb) bsum[t] = incl - v;
    if (t == nb - 1) *ptr_n = incl;
}

// merged pass 3: add block offset; write both ptr and off
__global__ void scan3_kernel() {
    bool isU = blockIdx.x < NB_U;
    int lb = isU ? blockIdx.x : blockIdx.x - NB_U;
    int n  = isU ? NU : NP;
    int* ptr = isU ? g_up_ptr : g_pu_ptr;
    int* off = isU ? g_up_off : g_pu_off;
    const int* bsum = isU ? g_bsum_u : g_bsum_p;

    int i = lb * 1024 + threadIdx.x;
    if (i < n) {
        int v = off[i] + bsum[lb];
        ptr[i] = v;
        off[i] = v;
    }
}

// ---------------- launch A: scatter UP entries || cvt pois -> bf16 ----------
__global__ void scatter_up_cvt_kernel(const int* __restrict__ up_rows,
                                      const int* __restrict__ up_cols,
                                      const float* __restrict__ up_vals,
                                      const float4* __restrict__ pois) {
    if (blockIdx.x < SC_BLOCKS) {
        int e = blockIdx.x * 256 + threadIdx.x;
        if (e >= NNZE) return;
        int r = __ldg(up_rows + e);
        int p = atomicAdd(&g_up_off[r], 1);
        g_up_cv[p] = make_int2(__ldg(up_cols + e), __float_as_int(__ldg(up_vals + e)));
    } else {
        int i = (blockIdx.x - SC_BLOCKS) * 256 + threadIdx.x;  // < NTOT/4 exact
        float4 v = pois[i];
        g_xh[2 * i]     = __floats2bfloat162_rn(v.x, v.y);
        g_xh[2 * i + 1] = __floats2bfloat162_rn(v.z, v.w);
    }
}

// ---------------- UP SpMM body: half-warp per U-row (two rows per warp) -----
// lane = 16*h + sl; half-warp h owns row w = 2*g + h.
// lane gathers uint2 (4 bf16) at positions [sl*4, sl*4+4) of the x row;
// writes one uint2 (4 bf16) of the msg row. No reductions, no tails.
__device__ __forceinline__ void spmm_up_body(int g, int lane) {
    int h = lane >> 4, sl = lane & 15;
    int w = 2 * g + h;                                   // < NU
    int s = __ldg(g_up_ptr + w), e = __ldg(g_up_ptr + w + 1);
    float a0 = 0.f, a1 = 0.f, a2 = 0.f, a3 = 0.f;
    const uint2* xbase = reinterpret_cast<const uint2*>(g_xh);
    for (int j = s; j < e; ++j) {
        int2 cv = __ldg(g_up_cv + j);                // same addr in half-warp: broadcast
        float v = __int_as_float(cv.y);
        uint2 raw = __ldg(xbase + (size_t)cv.x * 16 + sl);
        float2 p0 = bf2f(raw.x), p1 = bf2f(raw.y);
        a0 += v * p0.x; a1 += v * p0.y;
        a2 += v * p1.x; a3 += v * p1.y;
    }
    uint2 o;
    __nv_bfloat162 o0 = __floats2bfloat162_rn(a0, a1);
    __nv_bfloat162 o1 = __floats2bfloat162_rn(a2, a3);
    o.x = *reinterpret_cast<uint32_t*>(&o0);
    o.y = *reinterpret_cast<uint32_t*>(&o1);
    reinterpret_cast<uint2*>(g_msgh)[(size_t)w * 16 + sl] = o;
}

// ---------------- launch B: UP SpMM layer 0 || scatter PU entries ----------
__global__ void up0_scatter_pu_kernel(const int* __restrict__ pu_rows,
                                      const int* __restrict__ pu_cols,
                                      const float* __restrict__ pu_vals) {
    if (blockIdx.x < UP_BLOCKS) {
        int g = (blockIdx.x * 256 + threadIdx.x) >> 5;   // < NU/2 exact
        spmm_up_body(g, threadIdx.x & 31);
    } else {
        int e = (blockIdx.x - UP_BLOCKS) * 256 + threadIdx.x;
        if (e >= NNZE) return;
        int r = __ldg(pu_rows + e);
        int p = atomicAdd(&g_pu_off[r], 1);
        g_pu_cv[p] = make_int2(__ldg(pu_cols + e), __float_as_int(__ldg(pu_vals + e)));
    }
}

// plain UP SpMM for layers 1, 2
__global__ void spmm_up_kernel() {
    int g = (blockIdx.x * 256 + threadIdx.x) >> 5;       // < NU/2 exact
    spmm_up_body(g, threadIdx.x & 31);
}

// ---------------- PU SpMM fused: half-warp per row (two independent rows) ---
// lane = 16*h + sl; half-warp h owns row w = 2*g + h (g = global half-pair id).
// lane gathers uint2 (4 bf16) at positions [sl*4, sl*4+4) of the msg row.
// Epilogue: float4 on elements [w*64 + sl*4, +4); threefry inline (exact).
__global__ void spmm_pu_fused_kernel(const float* __restrict__ x_in,
                                     float* __restrict__ x_out,
                                     const float* __restrict__ pois_in,
                                     const float* __restrict__ x1_in,
                                     uint32_t k0, uint32_t k1, int last,
                                     float* __restrict__ out) {
    int g = (blockIdx.x * 256 + threadIdx.x) >> 5;       // < NP/2 exact
    int lane = threadIdx.x & 31;
    int h = lane >> 4, sl = lane & 15;
    int w = 2 * g + h;                                   // this half-warp's row
    int s = __ldg(g_pu_ptr + w), e = __ldg(g_pu_ptr + w + 1);
    float a0 = 0.f, a1 = 0.f, a2 = 0.f, a3 = 0.f;
    const uint2* mbase = reinterpret_cast<const uint2*>(g_msgh);
    for (int j = s; j < e; ++j) {
        int2 cv = __ldg(g_pu_cv + j);                // same addr in half-warp: broadcast
        float v = __int_as_float(cv.y);
        uint2 raw = __ldg(mbase + (size_t)cv.x * 16 + sl);
        float2 p0 = bf2f(raw.x), p1 = bf2f(raw.y);
        a0 += v * p0.x; a1 += v * p0.y;
        a2 += v * p1.x; a3 += v * p1.y;
    }

    size_t idx = (size_t)w * DIM + sl * 4;
    uint32_t e0 = (uint32_t)idx;
    uint32_t b0 = tf_bits(k0, k1, e0);
    uint32_t b1 = tf_bits(k0, k1, e0 + 1u);
    uint32_t b2 = tf_bits(k0, k1, e0 + 2u);
    uint32_t b3 = tf_bits(k0, k1, e0 + 3u);

    float4 xv = *reinterpret_cast<const float4*>(x_in + idx);
    float n0 = dropv(b0, a0 + xv.x);
    float n1 = dropv(b1, a1 + xv.y);
    float n2 = dropv(b2, a2 + xv.z);
    float n3 = dropv(b3, a3 + xv.w);

    if (last) {
        float4 pv = *reinterpret_cast<const float4*>(pois_in + idx);
        float4 x1 = *reinterpret_cast<const float4*>(x1_in + idx);
        *reinterpret_cast<float4*>(out + idx) =
            make_float4((pv.x + x1.x + xv.x + n0) * 0.25f,
                        (pv.y + x1.y + xv.y + n1) * 0.25f,
                        (pv.z + x1.z + xv.z + n2) * 0.25f,
                        (pv.w + x1.w + xv.w + n3) * 0.25f);
    } else {
        *reinterpret_cast<float4*>(x_out + idx) = make_float4(n0, n1, n2, n3);
        g_xh[idx / 2]     = __floats2bfloat162_rn(n0, n1);
        g_xh[idx / 2 + 1] = __floats2bfloat162_rn(n2, n3);
    }
}

// ---------------- launch ----------------
// Inputs in dict/insertion order:
//   d_in[0]=pois_embs, d_in[1]=up_rows, d_in[2]=up_cols, d_in[3]=up_vals,
//   d_in[4]=pu_rows,   d_in[5]=pu_cols, d_in[6]=pu_vals
extern "C" void kernel_launch(void* const* d_in, const int* in_sizes, int n_in,
                              void* d_out, int out_size) {
    const float* pois    = (const float*)d_in[0];
    const int*   up_rows = (const int*)  d_in[1];
    const int*   up_cols = (const int*)  d_in[2];
    const float* up_vals = (const float*)d_in[3];
    const int*   pu_rows = (const int*)  d_in[4];
    const int*   pu_cols = (const int*)  d_in[5];
    const float* pu_vals = (const float*)d_in[6];
    float* out = (float*)d_out;

    float *pxa, *pxb;
    cudaGetSymbolAddress((void**)&pxa, g_xa);
    cudaGetSymbolAddress((void**)&pxb, g_xb);

    // per-layer dropout keys: fold_in(key(42), l) = threefry((0,42),(0,l))
    uint32_t lk0[3], lk1[3];
    for (int l = 0; l < 3; ++l)
        tf2x32(0u, 42u, 0u, (uint32_t)l, lk0[l], lk1[l]);

    const int B = 256;

    // ---- CSR build (once per call, reused by all 3 layers) ----
    zero_cnt_kernel<<<(NP + 1 + B - 1) / B, B>>>();
    hist_kernel<<<SC_BLOCKS, B>>>(up_rows, pu_rows);
    scan1_kernel<<<NB_U + NB_P, 1024>>>();
    scan2_kernel<<<2, 256>>>();
    scan3_kernel<<<NB_U + NB_P, 1024>>>();

    // launch A: scatter UP || cvt pois->bf16
    scatter_up_cvt_kernel<<<SC_BLOCKS + CVT_BLOCKS, B>>>(up_rows, up_cols, up_vals,
                                                         (const float4*)pois);
    // launch B: UP SpMM layer 0 || scatter PU
    up0_scatter_pu_kernel<<<UP_BLOCKS + SC_BLOCKS, B>>>(pu_rows, pu_cols, pu_vals);

    // ---- layers (lazy acc: mean folded at last layer) ----
    // layer 0 PU: x_in = pois -> x1 in g_xa
    spmm_pu_fused_kernel<<<PU_BLOCKS, B>>>(pois, pxa, nullptr, nullptr,
                                           lk0[0], lk1[0], 0, out);
    // layer 1
    spmm_up_kernel<<<UP_BLOCKS, B>>>();
    spmm_pu_fused_kernel<<<PU_BLOCKS, B>>>(pxa, pxb, nullptr, nullptr,
                                           lk0[1], lk1[1], 0, out);
    // layer 2: out = 0.25*(pois + x1 + x2 + x3)
    spmm_up_kernel<<<UP_BLOCKS, B>>>();
    spmm_pu_fused_kernel<<<PU_BLOCKS, B>>>(pxb, nullptr, pois, pxa,
                                           lk0[2], lk1[2], 1, out);
}